// round 15
// baseline (speedup 1.0000x reference)
#include <cuda_runtime.h>
#include <math.h>

#define Nn    1152
#define Dd    64
#define Bb    16
#define Tt    1024
#define NSKEW 2016
#define CONDD 1152
#define MP    68
#define MPT   68
#define P1S   68
#define P2SY  68
#define P2SU  132
#define PW    16
#define PSTR  1156   // panel column stride (float4-aligned; consecutive-lane reads conflict-free)

typedef unsigned long long ull;

// ------------------ device scratch (no allocations allowed) ------------------
__device__ __align__(16) float g_At[Dd * Nn];       // Householder vectors, column j contiguous
__device__ __align__(16) float g_tau[Dd];
__device__ __align__(16) float g_T [4 * PW * PW];   // compact-WY T per panel
__device__ __align__(16) float g_U [Nn * Dd];       // U  [n][d]
__device__ __align__(16) float g_Ut[Dd * Nn];       // U^T [d][n]
__device__ __align__(16) float g_V [Bb * NSKEW];    // silu(cond) @ W^T + b
__device__ __align__(16) float g_RmI[Bb * Dd * Dd]; // R - I per batch, row-major [d][e]
__device__ __align__(16) float g_Y [Bb * Tt * Dd];  // (X U)(R-I)

// ------------------ packed f32x2 helpers (Blackwell FFMA2) ------------------
static __device__ __forceinline__ ull pack2(float x, float y) {
    ull r; asm("mov.b64 %0, {%1, %2};" : "=l"(r) : "f"(x), "f"(y)); return r;
}
static __device__ __forceinline__ void unpack2(ull p, float& x, float& y) {
    asm("mov.b64 {%0, %1}, %2;" : "=f"(x), "=f"(y) : "l"(p));
}
static __device__ __forceinline__ ull fma2(ull a, ull b, ull c) {
    ull d; asm("fma.rn.f32x2 %0, %1, %2, %3;" : "=l"(d) : "l"(a), "l"(b), "l"(c)); return d;
}

// =============================================================================
// Kernel 1a: blocked sgeqrf (panels of 16 + compact WY), LAPACK sign convention.
// One block, 1024 threads. ONE barrier per Householder step (fused stats).
// =============================================================================
__global__ void __launch_bounds__(1024) k_geqrf(const float* __restrict__ P) {
    extern __shared__ float V[];           // [PW][PSTR] raw panel, column-major
    __shared__ float sred[32];
    __shared__ float s_ts[PW];             // tau * scl^2
    __shared__ float s_scale[PW];          // scl = 1/(alpha-beta)
    __shared__ float s_beta[PW];
    __shared__ float s_tauv[PW];
    __shared__ float Tm[PW * PW];
    __shared__ float Sm[PW * PW];
    __shared__ float W1[PW * 48];
    __shared__ float W2[PW * 48];
    const int tid = threadIdx.x, lane = tid & 31, wid = tid >> 5;

    // load P^T: g_At[j][i] = P[i][j]
    for (int idx = tid; idx < Nn * Dd; idx += 1024) {
        int i = idx >> 6, j = idx & 63;
        g_At[j * Nn + i] = P[idx];
    }
    __syncthreads();

    for (int p = 0; p < 4; ++p) {
        const int j0 = p * PW;

        // ---- load panel into smem (float4) ----
        for (int f = tid; f < PW * (Nn / 4); f += 1024) {
            int c = f / (Nn / 4), i4 = f - c * (Nn / 4);
            ((float4*)(V + c * PSTR))[i4] =
                ((const float4*)(g_At + (size_t)(j0 + c) * Nn))[i4];
        }
        __syncthreads();

        // ---- prologue: reflector params for panel column 0 ----
        {
            float ssl = 0.f;
            for (int i = j0 + 1 + tid; i < Nn; i += 1024) { float a = V[i]; ssl += a * a; }
            #pragma unroll
            for (int o = 16; o; o >>= 1) ssl += __shfl_xor_sync(0xffffffffu, ssl, o);
            if (lane == 0) sred[wid] = ssl;
            __syncthreads();
            if (wid == 0) {
                float qv = sred[lane];
                #pragma unroll
                for (int o = 16; o; o >>= 1) qv += __shfl_xor_sync(0xffffffffu, qv, o);
                if (lane == 0) {
                    float alpha = V[j0];
                    float nrm = sqrtf(alpha * alpha + qv);
                    float beta = (alpha >= 0.f) ? -nrm : nrm;   // LAPACK
                    float tau = (beta - alpha) / beta;
                    float scl = 1.f / (alpha - beta);
                    s_ts[0] = tau * scl * scl; s_scale[0] = scl;
                    s_beta[0] = beta; s_tauv[0] = tau;
                    V[j0] = alpha - beta;                        // v_raw diag
                }
            }
        }

        // ---- 15 fused steps ----
        for (int jj = 0; jj < PW - 1; ++jj) {
            __syncthreads();
            const int j = j0 + jj;
            const int kcol = jj + 1 + wid;
            if (kcol < PW) {
                const float* vr = V + jj * PSTR;
                float* ck = V + kcol * PSTR;
                float dp = 0.f;
                for (int i = j + lane; i < Nn; i += 32) dp += vr[i] * ck[i];
                #pragma unroll
                for (int o = 16; o; o >>= 1) dp += __shfl_xor_sync(0xffffffffu, dp, o);
                const float coef = s_ts[jj] * dp;
                if (wid == 0) {
                    const int jn = j + 1;
                    float ssn = 0.f, alv = 0.f;
                    for (int i = j + lane; i < Nn; i += 32) {
                        float nv = ck[i] - coef * vr[i];
                        ck[i] = nv;
                        if (i > jn) ssn += nv * nv;
                        if (i == jn) alv = nv;
                    }
                    #pragma unroll
                    for (int o = 16; o; o >>= 1) ssn += __shfl_xor_sync(0xffffffffu, ssn, o);
                    #pragma unroll
                    for (int o = 16; o; o >>= 1) alv += __shfl_xor_sync(0xffffffffu, alv, o);
                    if (lane == 0) {
                        float nrm = sqrtf(alv * alv + ssn);
                        float beta = (alv >= 0.f) ? -nrm : nrm;   // LAPACK
                        float tau = (beta - alv) / beta;
                        float scl = 1.f / (alv - beta);
                        s_ts[jj + 1] = tau * scl * scl; s_scale[jj + 1] = scl;
                        s_beta[jj + 1] = beta; s_tauv[jj + 1] = tau;
                        ck[jn] = alv - beta;                      // v_raw diag
                    }
                } else {
                    for (int i = j + lane; i < Nn; i += 32) ck[i] -= coef * vr[i];
                }
            }
        }
        __syncthreads();

        // ---- write back (R + scaled reflectors) and normalize smem V for WY ----
        for (int idx = tid; idx < PW * Nn; idx += 1024) {
            int c = idx / Nn, i = idx - c * Nn;
            int diag = j0 + c;
            float val = V[c * PSTR + i];
            float outv, smv;
            if (i > diag)       { outv = val * s_scale[c]; smv = outv; }
            else if (i == diag) { outv = s_beta[c]; smv = 1.f; g_tau[diag] = s_tauv[c]; }
            else                { outv = val; smv = (i >= j0) ? 0.f : val; }
            g_At[(size_t)(j0 + c) * Nn + i] = outv;
            V[c * PSTR + i] = smv;
        }
        if (tid < PW * PW) { Tm[tid] = 0.f; Sm[tid] = 0.f; }
        __syncthreads();

        // ---- S[a][b] = v_a . v_b (a < b) ----
        for (int pr = wid; pr < PW * PW; pr += 32) {
            int a = pr >> 4, b2 = pr & 15;
            if (a < b2) {
                float dp = 0.f;
                for (int i = j0 + a + lane; i < Nn; i += 32)
                    dp += V[a * PSTR + i] * V[b2 * PSTR + i];
                #pragma unroll
                for (int o = 16; o; o >>= 1) dp += __shfl_xor_sync(0xffffffffu, dp, o);
                if (lane == 0) Sm[a * PW + b2] = dp;
            }
        }
        __syncthreads();

        // ---- build T (dlarft forward columnwise), warp 0 ----
        if (wid == 0) {
            for (int jj = 0; jj < PW; ++jj) {
                float t = 0.f;
                if (lane < jj) {
                    float acc = 0.f;
                    for (int m = 0; m < jj; ++m) acc += Tm[lane * PW + m] * Sm[m * PW + jj];
                    t = -s_tauv[jj] * acc;
                }
                __syncwarp();
                if (lane < jj) Tm[lane * PW + jj] = t;
                if (lane == jj) Tm[jj * PW + jj] = s_tauv[jj];
                __syncwarp();
            }
        }
        __syncthreads();
        if (tid < PW * PW) g_T[p * PW * PW + tid] = Tm[tid];

        // ---- trailing update: C <- C - V * T^T * (V^T C) ----
        const int nc = Dd - (j0 + PW);
        if (nc > 0) {
            for (int pr = wid; pr < PW * nc; pr += 32) {
                int a = pr / nc, k = pr - a * nc;
                const float* ck = g_At + (size_t)(j0 + PW + k) * Nn;
                float dp = 0.f;
                for (int i = j0 + a + lane; i < Nn; i += 32)
                    dp += V[a * PSTR + i] * ck[i];
                #pragma unroll
                for (int o = 16; o; o >>= 1) dp += __shfl_xor_sync(0xffffffffu, dp, o);
                if (lane == 0) W1[a * 48 + k] = dp;
            }
            __syncthreads();
            for (int idx = tid; idx < PW * nc; idx += 1024) {
                int b2 = idx / nc, k = idx - b2 * nc;
                float acc = 0.f;
                for (int a = 0; a <= b2; ++a) acc += Tm[a * PW + b2] * W1[a * 48 + k];
                W2[b2 * 48 + k] = acc;
            }
            __syncthreads();
            for (int i = j0 + tid; i < Nn; i += 1024) {
                float vv[PW];
                #pragma unroll
                for (int a = 0; a < PW; ++a) vv[a] = V[a * PSTR + i];
                for (int k = 0; k < nc; ++k) {
                    float acc = 0.f;
                    #pragma unroll
                    for (int a = 0; a < PW; ++a) acc += vv[a] * W2[a * 48 + k];
                    g_At[(size_t)(j0 + PW + k) * Nn + i] -= acc;
                }
            }
            __syncthreads();
        }
    }
}

// =============================================================================
// Kernel 1b: sorgqr, BATCHED: one block per 16-column panel-group (4 blocks,
// 512 threads). 16 boundary chains run in 16 parallel warps (barrier-free);
// lower panels applied via WY batched over all 16 columns (V loaded once).
// =============================================================================
__global__ void __launch_bounds__(512) k_orgqr() {
    extern __shared__ float sm[];
    float* Qs = sm;                      // [PW][PSTR] the 16 q columns
    float* Vp = sm + PW * PSTR;          // [PW][PSTR] current panel
    __shared__ float w[PW * PW], w2[PW * PW], staus[PW];
    const int tid = threadIdx.x, lane = tid & 31, wid = tid >> 5;   // 16 warps
    const int g = blockIdx.x;
    const int j0g = g * PW;

    // init Qs: column c = e_{j0g+c}
    for (int idx = tid; idx < PW * Nn; idx += 512) {
        int c = idx / Nn, i = idx - c * Nn;
        Qs[c * PSTR + i] = (i == j0g + c) ? 1.f : 0.f;
    }

    for (int p = g; p >= 0; --p) {
        const int j0 = p * PW;
        __syncthreads();
        // load panel p (float4) + taus
        for (int f = tid; f < PW * (Nn / 4); f += 512) {
            int c = f / (Nn / 4), i4 = f - c * (Nn / 4);
            ((float4*)(Vp + c * PSTR))[i4] =
                ((const float4*)(g_At + (size_t)(j0 + c) * Nn))[i4];
        }
        if (tid < PW) staus[tid] = g_tau[j0 + tid];
        __syncthreads();
        // fix 16x16 triangle: zeros above diag, unit diag
        if (tid < 256) {
            int c = tid >> 4, io = tid & 15;
            float* vv = Vp + c * PSTR + j0 + io;
            if (io < c)       *vv = 0.f;
            else if (io == c) *vv = 1.f;
        }
        __syncthreads();

        if (p == g) {
            // warp `wid` runs the serial chain for its own column (reflectors
            // j0+wid down to j0), entirely warp-local: no block barriers.
            float* q = Qs + wid * PSTR;
            for (int jj = wid; jj >= 0; --jj) {
                const float* v = Vp + jj * PSTR;
                const int j = j0 + jj;
                float dp = 0.f;
                for (int i = j + lane; i < Nn; i += 32) dp += v[i] * q[i];
                #pragma unroll
                for (int o = 16; o; o >>= 1) dp += __shfl_xor_sync(0xffffffffu, dp, o);
                const float coef = staus[jj] * dp;
                for (int i = j + lane; i < Nn; i += 32) q[i] -= coef * v[i];
            }
        } else {
            // ---- batched WY: Q -= V (T (V^T Q)) for all 16 columns ----
            // w[a][c] = v_a . q_c : warp a loads v_a once, FMAs into 16 accs
            {
                const int a = wid;
                const float* v = Vp + a * PSTR;
                float acc[PW];
                #pragma unroll
                for (int c = 0; c < PW; ++c) acc[c] = 0.f;
                for (int i = j0 + a + lane; i < Nn; i += 32) {
                    float va = v[i];
                    #pragma unroll
                    for (int c = 0; c < PW; ++c) acc[c] += va * Qs[c * PSTR + i];
                }
                #pragma unroll
                for (int c = 0; c < PW; ++c) {
                    #pragma unroll
                    for (int o = 16; o; o >>= 1)
                        acc[c] += __shfl_xor_sync(0xffffffffu, acc[c], o);
                }
                if (lane == 0) {
                    #pragma unroll
                    for (int c = 0; c < PW; ++c) w[a * PW + c] = acc[c];
                }
            }
            __syncthreads();
            // w2[a][c] = sum_{b>=a} T[a][b] w[b][c]
            if (tid < 256) {
                int a = tid >> 4, c = tid & 15;
                const float* Tp = g_T + p * PW * PW;
                float s = 0.f;
                for (int b2 = a; b2 < PW; ++b2) s += Tp[a * PW + b2] * w[b2 * PW + c];
                w2[a * PW + c] = s;
            }
            __syncthreads();
            // q_c -= V w2[:,c] : warp `wid` handles column wid
            {
                const int c = wid;
                float* q = Qs + c * PSTR;
                for (int i = j0 + lane; i < Nn; i += 32) {
                    float s = 0.f;
                    #pragma unroll
                    for (int a = 0; a < PW; ++a) s += Vp[a * PSTR + i] * w2[a * PW + c];
                    q[i] -= s;
                }
            }
        }
    }
    __syncthreads();
    for (int idx = tid; idx < PW * Nn; idx += 512) {
        int c = idx / Nn, i = idx - c * Nn;
        float val = Qs[c * PSTR + i];
        int k = j0g + c;
        g_Ut[(size_t)k * Nn + i] = val;
        g_U[(size_t)i * Dd + k]  = val;
    }
}

// =============================================================================
// Kernel 2: g_V[b][r] = dot(W[r], silu(cond[b])) + bias[r]  (split into 2
// launches via `off` so k_geqrf lands in profile slot 4)
// =============================================================================
__global__ void __launch_bounds__(256) k_v(const float* __restrict__ cond,
                                           const float* __restrict__ W,
                                           const float* __restrict__ bias,
                                           int off) {
    extern __shared__ float S[];   // [16][1152] silu(cond)
    const int tid = threadIdx.x, lane = tid & 31, wid = tid >> 5;
    for (int i = tid; i < Bb * CONDD; i += 256) {
        float c = cond[i];
        S[i] = c / (1.f + expf(-c));
    }
    __syncthreads();

    int r = (blockIdx.x + off) * 8 + wid;
    const float* wr = W + (size_t)r * CONDD;
    float acc[16];
    #pragma unroll
    for (int b = 0; b < 16; b++) acc[b] = 0.f;
    for (int c0 = 0; c0 < CONDD; c0 += 32) {
        float wv = wr[c0 + lane];
        #pragma unroll
        for (int b = 0; b < 16; b++) acc[b] += wv * S[b * CONDD + c0 + lane];
    }
    #pragma unroll
    for (int b = 0; b < 16; b++) {
        #pragma unroll
        for (int o = 16; o; o >>= 1) acc[b] += __shfl_xor_sync(0xffffffffu, acc[b], o);
    }
    if (lane == 0) {
        float bv = bias[r];
        #pragma unroll
        for (int b = 0; b < 16; b++) g_V[b * NSKEW + r] = acc[b] + bv;
    }
}

// =============================================================================
// Kernel 3: expm per batch (scaling & squaring + Taylor-Horner K=8).
// 16 blocks x 256 threads, 4x4 register tile per thread, FFMA2 inner loops.
// =============================================================================
static __device__ __forceinline__ void mm_horner(float* __restrict__ out,
                                                 const float* __restrict__ As,
                                                 const float* __restrict__ X,
                                                 float invk, int r0, int c0) {
    ull acc[4][2] = {};
    #pragma unroll 4
    for (int d = 0; d < 64; ++d) {
        float4 a4 = *(const float4*)(As + d * MP + r0);        // As[d][r] = -A[r][d]
        ulonglong2 bv = *(const ulonglong2*)(X + d * MP + c0);
        ull a0 = pack2(a4.x, a4.x), a1 = pack2(a4.y, a4.y);
        ull a2 = pack2(a4.z, a4.z), a3 = pack2(a4.w, a4.w);
        acc[0][0] = fma2(a0, bv.x, acc[0][0]); acc[0][1] = fma2(a0, bv.y, acc[0][1]);
        acc[1][0] = fma2(a1, bv.x, acc[1][0]); acc[1][1] = fma2(a1, bv.y, acc[1][1]);
        acc[2][0] = fma2(a2, bv.x, acc[2][0]); acc[2][1] = fma2(a2, bv.y, acc[2][1]);
        acc[3][0] = fma2(a3, bv.x, acc[3][0]); acc[3][1] = fma2(a3, bv.y, acc[3][1]);
    }
    const float nk = -invk;   // negate to undo the transposed-skew sign
    #pragma unroll
    for (int m = 0; m < 4; ++m) {
        float s0, s1, s2, s3;
        unpack2(acc[m][0], s0, s1);
        unpack2(acc[m][1], s2, s3);
        float4 o;
        o.x = nk * s0 + ((r0 + m == c0 + 0) ? 1.f : 0.f);
        o.y = nk * s1 + ((r0 + m == c0 + 1) ? 1.f : 0.f);
        o.z = nk * s2 + ((r0 + m == c0 + 2) ? 1.f : 0.f);
        o.w = nk * s3 + ((r0 + m == c0 + 3) ? 1.f : 0.f);
        *(float4*)(out + (r0 + m) * MP + c0) = o;
    }
}

static __device__ __forceinline__ void mm_sq(float* __restrict__ out,
                                             const float* __restrict__ XT,
                                             const float* __restrict__ X,
                                             int r0, int c0) {
    ull acc[4][2] = {};
    #pragma unroll 4
    for (int d = 0; d < 64; ++d) {
        float4 a4 = *(const float4*)(XT + d * MPT + r0);       // X[r0..r0+3][d]
        ulonglong2 bv = *(const ulonglong2*)(X + d * MP + c0);
        ull a0 = pack2(a4.x, a4.x), a1 = pack2(a4.y, a4.y);
        ull a2 = pack2(a4.z, a4.z), a3 = pack2(a4.w, a4.w);
        acc[0][0] = fma2(a0, bv.x, acc[0][0]); acc[0][1] = fma2(a0, bv.y, acc[0][1]);
        acc[1][0] = fma2(a1, bv.x, acc[1][0]); acc[1][1] = fma2(a1, bv.y, acc[1][1]);
        acc[2][0] = fma2(a2, bv.x, acc[2][0]); acc[2][1] = fma2(a2, bv.y, acc[2][1]);
        acc[3][0] = fma2(a3, bv.x, acc[3][0]); acc[3][1] = fma2(a3, bv.y, acc[3][1]);
    }
    #pragma unroll
    for (int m = 0; m < 4; ++m) {
        float s0, s1, s2, s3;
        unpack2(acc[m][0], s0, s1);
        unpack2(acc[m][1], s2, s3);
        *(float4*)(out + (r0 + m) * MP + c0) = make_float4(s0, s1, s2, s3);
    }
}

__global__ void __launch_bounds__(256) k_expm() {
    extern __shared__ float sm[];
    float* As = sm;                     // 64*68
    float* X0 = As + 64 * MP;
    float* X1 = X0 + 64 * MP;
    float* XT = X1 + 64 * MP;
    __shared__ float rowsum[64];
    __shared__ int s_s;
    const int tid = threadIdx.x;
    const int r0 = (tid >> 4) * 4, c0 = (tid & 15) * 4;
    const int b = blockIdx.x;
    const float* v = g_V + b * NSKEW;

    for (int t = tid; t < 4096; t += 256) {
        int i = t >> 6, j = t & 63;
        float val = 0.f;
        if (i < j)      val =  v[i * (127 - i) / 2 + (j - i - 1)];
        else if (i > j) val = -v[j * (127 - j) / 2 + (i - j - 1)];
        As[i * MP + j] = val;
    }
    __syncthreads();
    if (tid < 64) {
        float s = 0.f;
        for (int j = 0; j < 64; j++) s += fabsf(As[tid * MP + j]);
        rowsum[tid] = s;
    }
    __syncthreads();
    if (tid == 0) {
        float nrm = 0.f;
        for (int i = 0; i < 64; i++) nrm = fmaxf(nrm, rowsum[i]);
        int s = 0; float nn = nrm;
        while (nn > 0.5f && s < 40) { nn *= 0.5f; s++; }
        s_s = s;
    }
    __syncthreads();
    const int s = s_s;
    const float sc = exp2f((float)(-s));
    for (int t = tid; t < 4096; t += 256) { int i = t >> 6, j = t & 63; As[i * MP + j] *= sc; }
    __syncthreads();

    for (int t = tid; t < 4096; t += 256) {
        int i = t >> 6, j = t & 63;
        X0[i * MP + j] = ((i == j) ? 1.f : 0.f) + As[i * MP + j] * 0.125f;
    }
    float* Xa = X0; float* Xb = X1;
    for (int k = 7; k >= 1; --k) {
        __syncthreads();
        mm_horner(Xb, As, Xa, 1.f / (float)k, r0, c0);
        float* t = Xa; Xa = Xb; Xb = t;
    }
    for (int q = 0; q < s; q++) {
        __syncthreads();
        for (int t = tid; t < 4096; t += 256) {      // XT[j][i] = Xa[i][j]
            int i = t >> 6, j = t & 63;
            XT[j * MPT + i] = Xa[i * MP + j];
        }
        __syncthreads();
        mm_sq(Xb, XT, Xa, r0, c0);
        float* t = Xa; Xa = Xb; Xb = t;
    }
    __syncthreads();
    for (int t = tid; t < 4096; t += 256) {
        int i = t >> 6, j = t & 63;
        g_RmI[b * 4096 + t] = Xa[i * MP + j] - ((i == j) ? 1.f : 0.f);
    }
}

// =============================================================================
// Kernel 4: Y = (X U)(R - I).  64-row tiles, 256 blocks, 256 threads.
// =============================================================================
__global__ void __launch_bounds__(256) k_p1(const float* __restrict__ X,
                                            float* __restrict__ Y) {
    extern __shared__ float sm[];
    float* XsT = sm;                 // [64][68]  XsT[k][r]
    float* Us  = sm + 64 * P1S;      // [64][68]  Us[k][c]
    float* Ms  = Us + 64 * P1S;      // [64][68]  Ms[d][e]

    const int tid = threadIdx.x;
    const int rg = tid >> 4, cg = tid & 15;
    const int r0 = rg * 4, c0 = cg * 4;
    const size_t rowbase = (size_t)blockIdx.x * 64;
    const float* Xg = X + rowbase * Nn;
    const int b = blockIdx.x >> 4;

    const float* Mg = g_RmI + b * 4096;
    for (int i = tid; i < 4096; i += 256) {
        int d = i >> 6, e = i & 63;
        Ms[d * P1S + e] = Mg[i];
    }

    ull acc[4][2] = {};
    for (int kc = 0; kc < Nn; kc += 64) {
        __syncthreads();
        #pragma unroll
        for (int it = 0; it < 4; ++it) {
            int f4 = tid + 256 * it;
            int r  = f4 >> 4;
            int kq = (f4 & 15) * 4;
            float4 v = *(const float4*)(Xg + (size_t)r * Nn + kc + kq);
            XsT[(kq + 0) * P1S + r] = v.x;
            XsT[(kq + 1) * P1S + r] = v.y;
            XsT[(kq + 2) * P1S + r] = v.z;
            XsT[(kq + 3) * P1S + r] = v.w;
        }
        #pragma unroll
        for (int it = 0; it < 4; ++it) {
            int f4 = tid + 256 * it;
            int kk = f4 >> 4;
            int dq = (f4 & 15) * 4;
            float4 v = *(const float4*)(g_U + (size_t)(kc + kk) * Dd + dq);
            *(float4*)(Us + kk * P1S + dq) = v;
        }
        __syncthreads();
        #pragma unroll 4
        for (int k = 0; k < 64; ++k) {
            float4 xv = *(const float4*)(XsT + k * P1S + r0);
            ulonglong2 uv = *(const ulonglong2*)(Us + k * P1S + c0);
            ull x0 = pack2(xv.x, xv.x), x1 = pack2(xv.y, xv.y);
            ull x2 = pack2(xv.z, xv.z), x3 = pack2(xv.w, xv.w);
            acc[0][0] = fma2(x0, uv.x, acc[0][0]); acc[0][1] = fma2(x0, uv.y, acc[0][1]);
            acc[1][0] = fma2(x1, uv.x, acc[1][0]); acc[1][1] = fma2(x1, uv.y, acc[1][1]);
            acc[2][0] = fma2(x2, uv.x, acc[2][0]); acc[2][1] = fma2(x2, uv.y, acc[2][1]);
            acc[3][0] = fma2(x3, uv.x, acc[3][0]); acc[3][1] = fma2(x3, uv.y, acc[3][1]);
        }
    }
    __syncthreads();
    float* ZsT = XsT;
    #pragma unroll
    for (int m = 0; m < 4; ++m) {
        float a0, a1;
        unpack2(acc[m][0], a0, a1);
        ZsT[(c0 + 0) * P1S + r0 + m] = a0;
        ZsT[(c0 + 1) * P1S + r0 + m] = a1;
        unpack2(acc[m][1], a0, a1);
        ZsT[(c0 + 2) * P1S + r0 + m] = a0;
        ZsT[(c0 + 3) * P1S + r0 + m] = a1;
    }
    __syncthreads();
    ull yac[4][2] = {};
    #pragma unroll 4
    for (int d = 0; d < 64; ++d) {
        float4 zv = *(const float4*)(ZsT + d * P1S + r0);
        ulonglong2 mv = *(const ulonglong2*)(Ms + d * P1S + c0);
        ull z0 = pack2(zv.x, zv.x), z1 = pack2(zv.y, zv.y);
        ull z2 = pack2(zv.z, zv.z), z3 = pack2(zv.w, zv.w);
        yac[0][0] = fma2(z0, mv.x, yac[0][0]); yac[0][1] = fma2(z0, mv.y, yac[0][1]);
        yac[1][0] = fma2(z1, mv.x, yac[1][0]); yac[1][1] = fma2(z1, mv.y, yac[1][1]);
        yac[2][0] = fma2(z2, mv.x, yac[2][0]); yac[2][1] = fma2(z2, mv.y, yac[2][1]);
        yac[3][0] = fma2(z3, mv.x, yac[3][0]); yac[3][1] = fma2(z3, mv.y, yac[3][1]);
    }
    #pragma unroll
    for (int m = 0; m < 4; ++m) {
        float e0, e1, e2, e3;
        unpack2(yac[m][0], e0, e1);
        unpack2(yac[m][1], e2, e3);
        *(float4*)(Y + (rowbase + r0 + m) * Dd + c0) = make_float4(e0, e1, e2, e3);
    }
}

// =============================================================================
// Kernel 5: out = X + Y U^T.  Block tile 64 rows x 128 n-cols; grid (9, 256).
// =============================================================================
__global__ void __launch_bounds__(256) k_p2(const float* __restrict__ X,
                                            const float* __restrict__ Y,
                                            float* __restrict__ out) {
    extern __shared__ float sm[];
    float* YsT = sm;                 // [64][68]
    float* Uts = sm + 64 * P2SY;     // [64][132]

    const int tid = threadIdx.x;
    const int rg = tid >> 4, cg = tid & 15;
    const int r0 = rg * 4;
    const int n0 = cg * 8;
    const size_t rowbase = (size_t)blockIdx.y * 64;
    const int nbase = blockIdx.x * 128;

    #pragma unroll
    for (int it = 0; it < 4; ++it) {
        int f4 = tid + 256 * it;
        int r  = f4 >> 4;
        int dq = (f4 & 15) * 4;
        float4 v = *(const float4*)(Y + (rowbase + r) * Dd + dq);
        YsT[(dq + 0) * P2SY + r] = v.x;
        YsT[(dq + 1) * P2SY + r] = v.y;
        YsT[(dq + 2) * P2SY + r] = v.z;
        YsT[(dq + 3) * P2SY + r] = v.w;
    }
    #pragma unroll
    for (int it = 0; it < 8; ++it) {
        int f4 = tid + 256 * it;
        int d  = f4 >> 5;
        int nq = (f4 & 31) * 4;
        float4 v = *(const float4*)(g_Ut + (size_t)d * Nn + nbase + nq);
        *(float4*)(Uts + d * P2SU + nq) = v;
    }
    __syncthreads();

    ull acc[4][4] = {};
    #pragma unroll 4
    for (int d = 0; d < 64; ++d) {
        float4 yv = *(const float4*)(YsT + d * P2SY + r0);
        ulonglong2 u0 = *(const ulonglong2*)(Uts + d * P2SU + n0);
        ulonglong2 u1 = *(const ulonglong2*)(Uts + d * P2SU + n0 + 4);
        ull y0 = pack2(yv.x, yv.x), y1 = pack2(yv.y, yv.y);
        ull y2 = pack2(yv.z, yv.z), y3 = pack2(yv.w, yv.w);
        acc[0][0] = fma2(y0, u0.x, acc[0][0]); acc[0][1] = fma2(y0, u0.y, acc[0][1]);
        acc[0][2] = fma2(y0, u1.x, acc[0][2]); acc[0][3] = fma2(y0, u1.y, acc[0][3]);
        acc[1][0] = fma2(y1, u0.x, acc[1][0]); acc[1][1] = fma2(y1, u0.y, acc[1][1]);
        acc[1][2] = fma2(y1, u1.x, acc[1][2]); acc[1][3] = fma2(y1, u1.y, acc[1][3]);
        acc[2][0] = fma2(y2, u0.x, acc[2][0]); acc[2][1] = fma2(y2, u0.y, acc[2][1]);
        acc[2][2] = fma2(y2, u1.x, acc[2][2]); acc[2][3] = fma2(y2, u1.y, acc[2][3]);
        acc[3][0] = fma2(y3, u0.x, acc[3][0]); acc[3][1] = fma2(y3, u0.y, acc[3][1]);
        acc[3][2] = fma2(y3, u1.x, acc[3][2]); acc[3][3] = fma2(y3, u1.y, acc[3][3]);
    }

    #pragma unroll
    for (int m = 0; m < 4; ++m) {
        const size_t row = rowbase + r0 + m;
        const float* xr = X + row * Nn + nbase + n0;
        float* orow = out + row * Nn + nbase + n0;
        float4 xa = *(const float4*)(xr);
        float4 xb = *(const float4*)(xr + 4);
        float e0, e1, e2, e3;
        unpack2(acc[m][0], e0, e1); unpack2(acc[m][1], e2, e3);
        *(float4*)(orow) = make_float4(xa.x + e0, xa.y + e1, xa.z + e2, xa.w + e3);
        unpack2(acc[m][2], e0, e1); unpack2(acc[m][3], e2, e3);
        *(float4*)(orow + 4) = make_float4(xb.x + e0, xb.y + e1, xb.z + e2, xb.w + e3);
    }
}

// =============================================================================
extern "C" void kernel_launch(void* const* d_in, const int* in_sizes, int n_in,
                              void* d_out, int out_size) {
    const float* x    = (const float*)d_in[0];
    const float* cond = (const float*)d_in[1];
    const float* P    = (const float*)d_in[2];
    const float* W    = (const float*)d_in[3];
    const float* bias = (const float*)d_in[4];
    float* out = (float*)d_out;

    float* Yg = nullptr;
    cudaGetSymbolAddress((void**)&Yg, g_Y);

    const int smem_qr    = PW * PSTR * 4;                 // 73984
    const int smem_orgqr = 2 * PW * PSTR * 4;             // 147968
    const int smem_v     = Bb * CONDD * 4;                // 73728
    const int smem_expm  = (3 * MP + MPT) * 64 * 4;       // 69632
    const int smem_p1    = 3 * 64 * P1S * 4;              // 52224
    const int smem_p2    = 64 * P2SY * 4 + 64 * P2SU * 4; // 51200

    cudaFuncSetAttribute(k_geqrf, cudaFuncAttributeMaxDynamicSharedMemorySize, smem_qr);
    cudaFuncSetAttribute(k_orgqr, cudaFuncAttributeMaxDynamicSharedMemorySize, smem_orgqr);
    cudaFuncSetAttribute(k_v,    cudaFuncAttributeMaxDynamicSharedMemorySize, smem_v);
    cudaFuncSetAttribute(k_expm, cudaFuncAttributeMaxDynamicSharedMemorySize, smem_expm);
    cudaFuncSetAttribute(k_p1,   cudaFuncAttributeMaxDynamicSharedMemorySize, smem_p1);
    cudaFuncSetAttribute(k_p2,   cudaFuncAttributeMaxDynamicSharedMemorySize, smem_p2);

    // Order chosen so k_geqrf lands in profile slot #4 (ncu captures launch 4).
    k_v    <<<126, 256, smem_v>>>(cond, W, bias, 0);
    k_v    <<<126, 256, smem_v>>>(cond, W, bias, 126);
    k_expm <<<Bb, 256, smem_expm>>>();
    k_geqrf<<<1, 1024, smem_qr>>>(P);
    k_orgqr<<<4, 512, smem_orgqr>>>();
    k_p1   <<<(Bb * Tt) / 64, 256, smem_p1>>>(x, Yg);
    dim3 g2(Nn / 128, (Bb * Tt) / 64);
    k_p2   <<<g2, 256, smem_p2>>>(x, Yg, out);
}

// round 16
// speedup vs baseline: 1.7505x; 1.7505x over previous
#include <cuda_runtime.h>
#include <math.h>

#define Nn    1152
#define Dd    64
#define Bb    16
#define Tt    1024
#define NSKEW 2016
#define CONDD 1152
#define MP    68
#define MPT   68
#define P1S   68
#define P2SY  68
#define P2SU  132
#define GPARTS 18
#define RS    65     // rsign smem row stride

typedef unsigned long long ull;

// ------------------ device scratch (no allocations allowed) ------------------
__device__ __align__(16) float g_Gpart[GPARTS * 4096]; // partial Gram sums
__device__ __align__(16) float g_Rinv[4096];           // R^{-1} (upper tri inverse)
__device__ __align__(16) float g_U [Nn * Dd];          // U  [n][d]
__device__ __align__(16) float g_Ut[Dd * Nn];          // U^T [d][n]
__device__ __align__(16) float g_V [Bb * NSKEW];       // silu(cond) @ W^T + b
__device__ __align__(16) float g_RmI[Bb * Dd * Dd];    // R - I per batch
__device__ __align__(16) float g_Y [Bb * Tt * Dd];     // (X U)(R-I)

// ------------------ packed f32x2 helpers (Blackwell FFMA2) ------------------
static __device__ __forceinline__ ull pack2(float x, float y) {
    ull r; asm("mov.b64 %0, {%1, %2};" : "=l"(r) : "f"(x), "f"(y)); return r;
}
static __device__ __forceinline__ void unpack2(ull p, float& x, float& y) {
    asm("mov.b64 {%0, %1}, %2;" : "=f"(x), "=f"(y) : "l"(p));
}
static __device__ __forceinline__ ull fma2(ull a, ull b, ull c) {
    ull d; asm("fma.rn.f32x2 %0, %1, %2, %3;" : "=l"(d) : "l"(a), "l"(b), "l"(c)); return d;
}

// =============================================================================
// Kernel 1: fused  [blocks 0..251]  g_V[b][r] = dot(W[r], silu(cond[b])) + bias
//                  [blocks 252..269] partial Gram G_part = Pchunk^T Pchunk
// =============================================================================
__global__ void __launch_bounds__(256) k_prep0(const float* __restrict__ cond,
                                               const float* __restrict__ W,
                                               const float* __restrict__ bias,
                                               const float* __restrict__ P) {
    extern __shared__ float S[];
    const int tid = threadIdx.x, lane = tid & 31, wid = tid >> 5;

    if (blockIdx.x < 252) {
        // ---- silu(cond) @ W^T + b ----
        for (int i = tid; i < Bb * CONDD; i += 256) {
            float c = cond[i];
            S[i] = c / (1.f + expf(-c));
        }
        __syncthreads();
        int r = blockIdx.x * 8 + wid;
        const float* wr = W + (size_t)r * CONDD;
        float acc[16];
        #pragma unroll
        for (int b = 0; b < 16; b++) acc[b] = 0.f;
        for (int c0 = 0; c0 < CONDD; c0 += 32) {
            float wv = wr[c0 + lane];
            #pragma unroll
            for (int b = 0; b < 16; b++) acc[b] += wv * S[b * CONDD + c0 + lane];
        }
        #pragma unroll
        for (int b = 0; b < 16; b++) {
            #pragma unroll
            for (int o = 16; o; o >>= 1) acc[b] += __shfl_xor_sync(0xffffffffu, acc[b], o);
        }
        if (lane == 0) {
            float bv = bias[r];
            #pragma unroll
            for (int b = 0; b < 16; b++) g_V[b * NSKEW + r] = acc[b] + bv;
        }
    } else {
        // ---- partial Gram over 64 rows of P ----
        const int bk = blockIdx.x - 252;          // 0..17
        float* Ps = S;                             // [64][68]
        for (int f = tid; f < 64 * 16; f += 256) {
            int r = f >> 4, c4 = (f & 15) * 4;
            *(float4*)(Ps + r * 68 + c4) =
                *(const float4*)(P + (size_t)(bk * 64 + r) * Dd + c4);
        }
        __syncthreads();
        const int a0 = (tid >> 4) * 4, b0 = (tid & 15) * 4;
        float acc[4][4] = {};
        #pragma unroll 4
        for (int r = 0; r < 64; ++r) {
            float4 av = *(const float4*)(Ps + r * 68 + a0);
            float4 bv = *(const float4*)(Ps + r * 68 + b0);
            acc[0][0] += av.x * bv.x; acc[0][1] += av.x * bv.y; acc[0][2] += av.x * bv.z; acc[0][3] += av.x * bv.w;
            acc[1][0] += av.y * bv.x; acc[1][1] += av.y * bv.y; acc[1][2] += av.y * bv.z; acc[1][3] += av.y * bv.w;
            acc[2][0] += av.z * bv.x; acc[2][1] += av.z * bv.y; acc[2][2] += av.z * bv.z; acc[2][3] += av.z * bv.w;
            acc[3][0] += av.w * bv.x; acc[3][1] += av.w * bv.y; acc[3][2] += av.w * bv.z; acc[3][3] += av.w * bv.w;
        }
        float* Gp = g_Gpart + bk * 4096;
        #pragma unroll
        for (int m = 0; m < 4; ++m)
            *(float4*)(Gp + (a0 + m) * 64 + b0) =
                make_float4(acc[m][0], acc[m][1], acc[m][2], acc[m][3]);
    }
}

// =============================================================================
// Kernel 2: sign-exact LAPACK R via top-block recursion, then R^{-1}.
// One block, 128 threads. B = P[0:64][:], G = sum of partial Grams,
// M = running sum R_k^T R_k.  Per step j (LAPACK conventions):
//   alpha = B[j][j]; nrm2 = G[j][j]-M[j][j]; beta = -sign(alpha)*sqrt(nrm2)
//   u = G[j,:] - M[j,:] - beta*B[j,:];  coef_i = tau*scl^2 * v_raw[i]
//   B[i,:] -= coef_i * u  (i>=j);  finalize row j; M += R_j^T R_j
// =============================================================================
__global__ void __launch_bounds__(128) k_rsign(const float* __restrict__ P) {
    extern __shared__ float sm[];
    float* B = sm;                  // [64][RS]
    float* G = sm + 64 * RS;        // [64][RS]
    float* M = sm + 2 * 64 * RS;    // [64][RS]  (reused as Rinv scratch)
    __shared__ float u[64], coef[64];
    __shared__ float s_beta, s_ts, s_amb;
    const int tid = threadIdx.x;

    for (int idx = tid; idx < 4096; idx += 128) {
        int i = idx >> 6, c = idx & 63;
        B[i * RS + c] = P[(size_t)i * Dd + c];
        float g = 0.f;
        #pragma unroll
        for (int t = 0; t < GPARTS; ++t) g += g_Gpart[t * 4096 + idx];
        G[i * RS + c] = g;
        M[i * RS + c] = 0.f;
    }
    __syncthreads();

    for (int j = 0; j < 64; ++j) {
        if (tid == 0) {
            float a = B[j * RS + j];
            float n2 = G[j * RS + j] - M[j * RS + j];
            float nrm = sqrtf(fmaxf(n2, 0.f));
            float beta = (a >= 0.f) ? -nrm : nrm;   // LAPACK sign convention
            float tau = (beta - a) / beta;
            float scl = 1.f / (a - beta);
            s_beta = beta; s_ts = tau * scl * scl; s_amb = a - beta;
        }
        __syncthreads();
        if (tid < 64) {
            int c = tid;
            u[c] = G[j * RS + c] - M[j * RS + c] - s_beta * B[j * RS + c];
        } else {
            int i = tid - 64;
            float vr;
            if (i > j)       vr = B[i * RS + j];
            else if (i == j) vr = s_amb;
            else             vr = 0.f;
            coef[i] = s_ts * vr;
        }
        __syncthreads();
        const int nrows = 64 - j;
        for (int idx = tid; idx < nrows * 64; idx += 128) {
            int i = j + (idx >> 6), c = idx & 63;
            B[i * RS + c] -= coef[i] * u[c];
        }
        __syncthreads();
        // finalize: exact beta on diag, exact zeros left of diag and below it
        if (tid < 64) {
            int c = tid;
            if (c < j)       B[j * RS + c] = 0.f;
            else if (c == j) B[j * RS + c] = s_beta;
        } else {
            int i = tid - 64;
            if (i > j) B[i * RS + j] = 0.f;
        }
        __syncthreads();
        for (int idx = tid; idx < 4096; idx += 128) {
            int a = idx >> 6, b2 = idx & 63;
            M[a * RS + b2] += B[j * RS + a] * B[j * RS + b2];
        }
        __syncthreads();
    }

    // ---- backward-substitution inverse of R (column per thread) ----
    float* X = M;   // reuse
    if (tid < 64) {
        const int c = tid;
        for (int i = 63; i >= 0; --i) {
            float s = (i == c) ? 1.f : 0.f;
            for (int k = i + 1; k < 64; ++k) s -= B[i * RS + k] * X[k * RS + c];
            X[i * RS + c] = s / B[i * RS + i];
        }
    }
    __syncthreads();
    for (int idx = tid; idx < 4096; idx += 128)
        g_Rinv[idx] = X[(idx >> 6) * RS + (idx & 63)];
}

// =============================================================================
// Kernel 3: fused  [blocks 0..17]  U = P * Rinv  (writes g_U and g_Ut)
//                  [blocks 18..33] expm per batch (b = blockIdx.x - 18)
// =============================================================================
static __device__ __forceinline__ void mm_horner(float* __restrict__ out,
                                                 const float* __restrict__ As,
                                                 const float* __restrict__ X,
                                                 float invk, int r0, int c0) {
    ull acc[4][2] = {};
    #pragma unroll 4
    for (int d = 0; d < 64; ++d) {
        float4 a4 = *(const float4*)(As + d * MP + r0);        // As[d][r] = -A[r][d]
        ulonglong2 bv = *(const ulonglong2*)(X + d * MP + c0);
        ull a0 = pack2(a4.x, a4.x), a1 = pack2(a4.y, a4.y);
        ull a2 = pack2(a4.z, a4.z), a3 = pack2(a4.w, a4.w);
        acc[0][0] = fma2(a0, bv.x, acc[0][0]); acc[0][1] = fma2(a0, bv.y, acc[0][1]);
        acc[1][0] = fma2(a1, bv.x, acc[1][0]); acc[1][1] = fma2(a1, bv.y, acc[1][1]);
        acc[2][0] = fma2(a2, bv.x, acc[2][0]); acc[2][1] = fma2(a2, bv.y, acc[2][1]);
        acc[3][0] = fma2(a3, bv.x, acc[3][0]); acc[3][1] = fma2(a3, bv.y, acc[3][1]);
    }
    const float nk = -invk;
    #pragma unroll
    for (int m = 0; m < 4; ++m) {
        float s0, s1, s2, s3;
        unpack2(acc[m][0], s0, s1);
        unpack2(acc[m][1], s2, s3);
        float4 o;
        o.x = nk * s0 + ((r0 + m == c0 + 0) ? 1.f : 0.f);
        o.y = nk * s1 + ((r0 + m == c0 + 1) ? 1.f : 0.f);
        o.z = nk * s2 + ((r0 + m == c0 + 2) ? 1.f : 0.f);
        o.w = nk * s3 + ((r0 + m == c0 + 3) ? 1.f : 0.f);
        *(float4*)(out + (r0 + m) * MP + c0) = o;
    }
}

static __device__ __forceinline__ void mm_sq(float* __restrict__ out,
                                             const float* __restrict__ XT,
                                             const float* __restrict__ X,
                                             int r0, int c0) {
    ull acc[4][2] = {};
    #pragma unroll 4
    for (int d = 0; d < 64; ++d) {
        float4 a4 = *(const float4*)(XT + d * MPT + r0);
        ulonglong2 bv = *(const ulonglong2*)(X + d * MP + c0);
        ull a0 = pack2(a4.x, a4.x), a1 = pack2(a4.y, a4.y);
        ull a2 = pack2(a4.z, a4.z), a3 = pack2(a4.w, a4.w);
        acc[0][0] = fma2(a0, bv.x, acc[0][0]); acc[0][1] = fma2(a0, bv.y, acc[0][1]);
        acc[1][0] = fma2(a1, bv.x, acc[1][0]); acc[1][1] = fma2(a1, bv.y, acc[1][1]);
        acc[2][0] = fma2(a2, bv.x, acc[2][0]); acc[2][1] = fma2(a2, bv.y, acc[2][1]);
        acc[3][0] = fma2(a3, bv.x, acc[3][0]); acc[3][1] = fma2(a3, bv.y, acc[3][1]);
    }
    #pragma unroll
    for (int m = 0; m < 4; ++m) {
        float s0, s1, s2, s3;
        unpack2(acc[m][0], s0, s1);
        unpack2(acc[m][1], s2, s3);
        *(float4*)(out + (r0 + m) * MP + c0) = make_float4(s0, s1, s2, s3);
    }
}

__global__ void __launch_bounds__(256) k_prep1(const float* __restrict__ P) {
    extern __shared__ float sm[];
    const int tid = threadIdx.x;

    if (blockIdx.x < 18) {
        // ---- U = P * Rinv over 64 rows ----
        float* PsT = sm;              // [64][68]  PsT[k][r]
        float* Ri  = sm + 64 * 68;    // [64][68]  Ri[k][d]
        const int n0 = blockIdx.x * 64;
        for (int f = tid; f < 64 * 16; f += 256) {
            int r = f >> 4, k4 = (f & 15) * 4;
            float4 v = *(const float4*)(P + (size_t)(n0 + r) * Dd + k4);
            PsT[(k4 + 0) * 68 + r] = v.x;
            PsT[(k4 + 1) * 68 + r] = v.y;
            PsT[(k4 + 2) * 68 + r] = v.z;
            PsT[(k4 + 3) * 68 + r] = v.w;
        }
        for (int f = tid; f < 64 * 16; f += 256) {
            int k = f >> 4, d4 = (f & 15) * 4;
            *(float4*)(Ri + k * 68 + d4) = *(const float4*)(g_Rinv + k * 64 + d4);
        }
        __syncthreads();
        const int r0 = (tid >> 4) * 4, d0 = (tid & 15) * 4;
        float acc[4][4] = {};
        #pragma unroll 4
        for (int k = 0; k < 64; ++k) {
            float4 av = *(const float4*)(PsT + k * 68 + r0);
            float4 bv = *(const float4*)(Ri + k * 68 + d0);
            acc[0][0] += av.x * bv.x; acc[0][1] += av.x * bv.y; acc[0][2] += av.x * bv.z; acc[0][3] += av.x * bv.w;
            acc[1][0] += av.y * bv.x; acc[1][1] += av.y * bv.y; acc[1][2] += av.y * bv.z; acc[1][3] += av.y * bv.w;
            acc[2][0] += av.z * bv.x; acc[2][1] += av.z * bv.y; acc[2][2] += av.z * bv.z; acc[2][3] += av.z * bv.w;
            acc[3][0] += av.w * bv.x; acc[3][1] += av.w * bv.y; acc[3][2] += av.w * bv.z; acc[3][3] += av.w * bv.w;
        }
        #pragma unroll
        for (int m = 0; m < 4; ++m) {
            int n = n0 + r0 + m;
            *(float4*)(g_U + (size_t)n * Dd + d0) =
                make_float4(acc[m][0], acc[m][1], acc[m][2], acc[m][3]);
            #pragma unroll
            for (int q = 0; q < 4; ++q)
                g_Ut[(size_t)(d0 + q) * Nn + n] = acc[m][q];
        }
    } else {
        // ---- expm, batch b ----
        float* As = sm;
        float* X0 = As + 64 * MP;
        float* X1 = X0 + 64 * MP;
        float* XT = X1 + 64 * MP;
        __shared__ float rowsum[64];
        __shared__ int s_s;
        const int r0 = (tid >> 4) * 4, c0 = (tid & 15) * 4;
        const int b = blockIdx.x - 18;
        const float* v = g_V + b * NSKEW;

        for (int t = tid; t < 4096; t += 256) {
            int i = t >> 6, j = t & 63;
            float val = 0.f;
            if (i < j)      val =  v[i * (127 - i) / 2 + (j - i - 1)];
            else if (i > j) val = -v[j * (127 - j) / 2 + (i - j - 1)];
            As[i * MP + j] = val;
        }
        __syncthreads();
        if (tid < 64) {
            float s = 0.f;
            for (int j = 0; j < 64; j++) s += fabsf(As[tid * MP + j]);
            rowsum[tid] = s;
        }
        __syncthreads();
        if (tid == 0) {
            float nrm = 0.f;
            for (int i = 0; i < 64; i++) nrm = fmaxf(nrm, rowsum[i]);
            int s = 0; float nn = nrm;
            while (nn > 0.5f && s < 40) { nn *= 0.5f; s++; }
            s_s = s;
        }
        __syncthreads();
        const int s = s_s;
        const float sc = exp2f((float)(-s));
        for (int t = tid; t < 4096; t += 256) { int i = t >> 6, j = t & 63; As[i * MP + j] *= sc; }
        __syncthreads();

        for (int t = tid; t < 4096; t += 256) {
            int i = t >> 6, j = t & 63;
            X0[i * MP + j] = ((i == j) ? 1.f : 0.f) + As[i * MP + j] * 0.125f;
        }
        float* Xa = X0; float* Xb = X1;
        for (int k = 7; k >= 1; --k) {
            __syncthreads();
            mm_horner(Xb, As, Xa, 1.f / (float)k, r0, c0);
            float* t = Xa; Xa = Xb; Xb = t;
        }
        for (int q = 0; q < s; q++) {
            __syncthreads();
            for (int t = tid; t < 4096; t += 256) {
                int i = t >> 6, j = t & 63;
                XT[j * MPT + i] = Xa[i * MP + j];
            }
            __syncthreads();
            mm_sq(Xb, XT, Xa, r0, c0);
            float* t = Xa; Xa = Xb; Xb = t;
        }
        __syncthreads();
        for (int t = tid; t < 4096; t += 256) {
            int i = t >> 6, j = t & 63;
            g_RmI[b * 4096 + t] = Xa[i * MP + j] - ((i == j) ? 1.f : 0.f);
        }
    }
}

// =============================================================================
// Kernel 4: Y = (X U)(R - I).  64-row tiles, 256 blocks, 256 threads.
// =============================================================================
__global__ void __launch_bounds__(256) k_p1(const float* __restrict__ X,
                                            float* __restrict__ Y) {
    extern __shared__ float sm[];
    float* XsT = sm;                 // [64][68]  XsT[k][r]
    float* Us  = sm + 64 * P1S;      // [64][68]  Us[k][c]
    float* Ms  = Us + 64 * P1S;      // [64][68]  Ms[d][e]

    const int tid = threadIdx.x;
    const int rg = tid >> 4, cg = tid & 15;
    const int r0 = rg * 4, c0 = cg * 4;
    const size_t rowbase = (size_t)blockIdx.x * 64;
    const float* Xg = X + rowbase * Nn;
    const int b = blockIdx.x >> 4;

    const float* Mg = g_RmI + b * 4096;
    for (int i = tid; i < 4096; i += 256) {
        int d = i >> 6, e = i & 63;
        Ms[d * P1S + e] = Mg[i];
    }

    ull acc[4][2] = {};
    for (int kc = 0; kc < Nn; kc += 64) {
        __syncthreads();
        #pragma unroll
        for (int it = 0; it < 4; ++it) {
            int f4 = tid + 256 * it;
            int r  = f4 >> 4;
            int kq = (f4 & 15) * 4;
            float4 v = *(const float4*)(Xg + (size_t)r * Nn + kc + kq);
            XsT[(kq + 0) * P1S + r] = v.x;
            XsT[(kq + 1) * P1S + r] = v.y;
            XsT[(kq + 2) * P1S + r] = v.z;
            XsT[(kq + 3) * P1S + r] = v.w;
        }
        #pragma unroll
        for (int it = 0; it < 4; ++it) {
            int f4 = tid + 256 * it;
            int kk = f4 >> 4;
            int dq = (f4 & 15) * 4;
            float4 v = *(const float4*)(g_U + (size_t)(kc + kk) * Dd + dq);
            *(float4*)(Us + kk * P1S + dq) = v;
        }
        __syncthreads();
        #pragma unroll 4
        for (int k = 0; k < 64; ++k) {
            float4 xv = *(const float4*)(XsT + k * P1S + r0);
            ulonglong2 uv = *(const ulonglong2*)(Us + k * P1S + c0);
            ull x0 = pack2(xv.x, xv.x), x1 = pack2(xv.y, xv.y);
            ull x2 = pack2(xv.z, xv.z), x3 = pack2(xv.w, xv.w);
            acc[0][0] = fma2(x0, uv.x, acc[0][0]); acc[0][1] = fma2(x0, uv.y, acc[0][1]);
            acc[1][0] = fma2(x1, uv.x, acc[1][0]); acc[1][1] = fma2(x1, uv.y, acc[1][1]);
            acc[2][0] = fma2(x2, uv.x, acc[2][0]); acc[2][1] = fma2(x2, uv.y, acc[2][1]);
            acc[3][0] = fma2(x3, uv.x, acc[3][0]); acc[3][1] = fma2(x3, uv.y, acc[3][1]);
        }
    }
    __syncthreads();
    float* ZsT = XsT;
    #pragma unroll
    for (int m = 0; m < 4; ++m) {
        float a0, a1;
        unpack2(acc[m][0], a0, a1);
        ZsT[(c0 + 0) * P1S + r0 + m] = a0;
        ZsT[(c0 + 1) * P1S + r0 + m] = a1;
        unpack2(acc[m][1], a0, a1);
        ZsT[(c0 + 2) * P1S + r0 + m] = a0;
        ZsT[(c0 + 3) * P1S + r0 + m] = a1;
    }
    __syncthreads();
    ull yac[4][2] = {};
    #pragma unroll 4
    for (int d = 0; d < 64; ++d) {
        float4 zv = *(const float4*)(ZsT + d * P1S + r0);
        ulonglong2 mv = *(const ulonglong2*)(Ms + d * P1S + c0);
        ull z0 = pack2(zv.x, zv.x), z1 = pack2(zv.y, zv.y);
        ull z2 = pack2(zv.z, zv.z), z3 = pack2(zv.w, zv.w);
        yac[0][0] = fma2(z0, mv.x, yac[0][0]); yac[0][1] = fma2(z0, mv.y, yac[0][1]);
        yac[1][0] = fma2(z1, mv.x, yac[1][0]); yac[1][1] = fma2(z1, mv.y, yac[1][1]);
        yac[2][0] = fma2(z2, mv.x, yac[2][0]); yac[2][1] = fma2(z2, mv.y, yac[2][1]);
        yac[3][0] = fma2(z3, mv.x, yac[3][0]); yac[3][1] = fma2(z3, mv.y, yac[3][1]);
    }
    #pragma unroll
    for (int m = 0; m < 4; ++m) {
        float e0, e1, e2, e3;
        unpack2(yac[m][0], e0, e1);
        unpack2(yac[m][1], e2, e3);
        *(float4*)(Y + (rowbase + r0 + m) * Dd + c0) = make_float4(e0, e1, e2, e3);
    }
}

// =============================================================================
// Kernel 5: out = X + Y U^T.  Block tile 64 rows x 128 n-cols; grid (9, 256).
// =============================================================================
__global__ void __launch_bounds__(256) k_p2(const float* __restrict__ X,
                                            const float* __restrict__ Y,
                                            float* __restrict__ out) {
    extern __shared__ float sm[];
    float* YsT = sm;                 // [64][68]
    float* Uts = sm + 64 * P2SY;     // [64][132]

    const int tid = threadIdx.x;
    const int rg = tid >> 4, cg = tid & 15;
    const int r0 = rg * 4;
    const int n0 = cg * 8;
    const size_t rowbase = (size_t)blockIdx.y * 64;
    const int nbase = blockIdx.x * 128;

    #pragma unroll
    for (int it = 0; it < 4; ++it) {
        int f4 = tid + 256 * it;
        int r  = f4 >> 4;
        int dq = (f4 & 15) * 4;
        float4 v = *(const float4*)(Y + (rowbase + r) * Dd + dq);
        YsT[(dq + 0) * P2SY + r] = v.x;
        YsT[(dq + 1) * P2SY + r] = v.y;
        YsT[(dq + 2) * P2SY + r] = v.z;
        YsT[(dq + 3) * P2SY + r] = v.w;
    }
    #pragma unroll
    for (int it = 0; it < 8; ++it) {
        int f4 = tid + 256 * it;
        int d  = f4 >> 5;
        int nq = (f4 & 31) * 4;
        float4 v = *(const float4*)(g_Ut + (size_t)d * Nn + nbase + nq);
        *(float4*)(Uts + d * P2SU + nq) = v;
    }
    __syncthreads();

    ull acc[4][4] = {};
    #pragma unroll 4
    for (int d = 0; d < 64; ++d) {
        float4 yv = *(const float4*)(YsT + d * P2SY + r0);
        ulonglong2 u0 = *(const ulonglong2*)(Uts + d * P2SU + n0);
        ulonglong2 u1 = *(const ulonglong2*)(Uts + d * P2SU + n0 + 4);
        ull y0 = pack2(yv.x, yv.x), y1 = pack2(yv.y, yv.y);
        ull y2 = pack2(yv.z, yv.z), y3 = pack2(yv.w, yv.w);
        acc[0][0] = fma2(y0, u0.x, acc[0][0]); acc[0][1] = fma2(y0, u0.y, acc[0][1]);
        acc[0][2] = fma2(y0, u1.x, acc[0][2]); acc[0][3] = fma2(y0, u1.y, acc[0][3]);
        acc[1][0] = fma2(y1, u0.x, acc[1][0]); acc[1][1] = fma2(y1, u0.y, acc[1][1]);
        acc[1][2] = fma2(y1, u1.x, acc[1][2]); acc[1][3] = fma2(y1, u1.y, acc[1][3]);
        acc[2][0] = fma2(y2, u0.x, acc[2][0]); acc[2][1] = fma2(y2, u0.y, acc[2][1]);
        acc[2][2] = fma2(y2, u1.x, acc[2][2]); acc[2][3] = fma2(y2, u1.y, acc[2][3]);
        acc[3][0] = fma2(y3, u0.x, acc[3][0]); acc[3][1] = fma2(y3, u0.y, acc[3][1]);
        acc[3][2] = fma2(y3, u1.x, acc[3][2]); acc[3][3] = fma2(y3, u1.y, acc[3][3]);
    }

    #pragma unroll
    for (int m = 0; m < 4; ++m) {
        const size_t row = rowbase + r0 + m;
        const float* xr = X + row * Nn + nbase + n0;
        float* orow = out + row * Nn + nbase + n0;
        float4 xa = *(const float4*)(xr);
        float4 xb = *(const float4*)(xr + 4);
        float e0, e1, e2, e3;
        unpack2(acc[m][0], e0, e1); unpack2(acc[m][1], e2, e3);
        *(float4*)(orow) = make_float4(xa.x + e0, xa.y + e1, xa.z + e2, xa.w + e3);
        unpack2(acc[m][2], e0, e1); unpack2(acc[m][3], e2, e3);
        *(float4*)(orow + 4) = make_float4(xb.x + e0, xb.y + e1, xb.z + e2, xb.w + e3);
    }
}

// =============================================================================
extern "C" void kernel_launch(void* const* d_in, const int* in_sizes, int n_in,
                              void* d_out, int out_size) {
    const float* x    = (const float*)d_in[0];
    const float* cond = (const float*)d_in[1];
    const float* P    = (const float*)d_in[2];
    const float* W    = (const float*)d_in[3];
    const float* bias = (const float*)d_in[4];
    float* out = (float*)d_out;

    float* Yg = nullptr;
    cudaGetSymbolAddress((void**)&Yg, g_Y);

    const int smem_prep0 = Bb * CONDD * 4;                 // 73728
    const int smem_rsign = 3 * 64 * RS * 4;                // 49920
    const int smem_prep1 = (3 * MP + MPT) * 64 * 4;        // 69632
    const int smem_p1    = 3 * 64 * P1S * 4;               // 52224
    const int smem_p2    = 64 * P2SY * 4 + 64 * P2SU * 4;  // 51200

    cudaFuncSetAttribute(k_prep0, cudaFuncAttributeMaxDynamicSharedMemorySize, smem_prep0);
    cudaFuncSetAttribute(k_rsign, cudaFuncAttributeMaxDynamicSharedMemorySize, smem_rsign);
    cudaFuncSetAttribute(k_prep1, cudaFuncAttributeMaxDynamicSharedMemorySize, smem_prep1);
    cudaFuncSetAttribute(k_p1,    cudaFuncAttributeMaxDynamicSharedMemorySize, smem_p1);
    cudaFuncSetAttribute(k_p2,    cudaFuncAttributeMaxDynamicSharedMemorySize, smem_p2);

    // Kernel order: p1 lands in profile slot #4 for next round's capture.
    k_prep0<<<252 + GPARTS, 256, smem_prep0>>>(cond, W, bias, P);
    k_rsign<<<1, 128, smem_rsign>>>(P);
    k_prep1<<<18 + Bb, 256, smem_prep1>>>(P);
    k_p1   <<<(Bb * Tt) / 64, 256, smem_p1>>>(x, Yg);
    dim3 g2(Nn / 128, (Bb * Tt) / 64);
    k_p2   <<<g2, 256, smem_p2>>>(x, Yg, out);
}

// round 17
// speedup vs baseline: 1.8093x; 1.0336x over previous
#include <cuda_runtime.h>
#include <math.h>

#define Nn    1152
#define Dd    64
#define Bb    16
#define Tt    1024
#define NSKEW 2016
#define CONDD 1152
#define MP    68
#define MPT   68
#define P1S   68
#define P2SY  68
#define P2SU  132
#define GPARTS 18
#define RS    65     // rsign smem row stride

typedef unsigned long long ull;

// ------------------ device scratch (no allocations allowed) ------------------
__device__ __align__(16) float g_Gpart[GPARTS * 4096]; // partial Gram sums
__device__ __align__(16) float g_Rinv[4096];           // R^{-1} (upper tri inverse)
__device__ __align__(16) float g_U [Nn * Dd];          // U  [n][d]
__device__ __align__(16) float g_Ut[Dd * Nn];          // U^T [d][n]
__device__ __align__(16) float g_V [Bb * NSKEW];       // silu(cond) @ W^T + b
__device__ __align__(16) float g_RmI[Bb * Dd * Dd];    // R - I per batch
__device__ __align__(16) float g_Y [Bb * Tt * Dd];     // (X U)(R-I)

// ------------------ packed f32x2 helpers (Blackwell FFMA2) ------------------
static __device__ __forceinline__ ull pack2(float x, float y) {
    ull r; asm("mov.b64 %0, {%1, %2};" : "=l"(r) : "f"(x), "f"(y)); return r;
}
static __device__ __forceinline__ void unpack2(ull p, float& x, float& y) {
    asm("mov.b64 {%0, %1}, %2;" : "=f"(x), "=f"(y) : "l"(p));
}
static __device__ __forceinline__ ull fma2(ull a, ull b, ull c) {
    ull d; asm("fma.rn.f32x2 %0, %1, %2, %3;" : "=l"(d) : "l"(a), "l"(b), "l"(c)); return d;
}

// =============================================================================
// Kernel 1: fused  [blocks 0..251]  g_V[b][r] = dot(W[r], silu(cond[b])) + bias
//                  [blocks 252..269] partial Gram G_part = Pchunk^T Pchunk
// =============================================================================
__global__ void __launch_bounds__(256) k_prep0(const float* __restrict__ cond,
                                               const float* __restrict__ W,
                                               const float* __restrict__ bias,
                                               const float* __restrict__ P) {
    extern __shared__ float S[];
    const int tid = threadIdx.x, lane = tid & 31, wid = tid >> 5;

    if (blockIdx.x < 252) {
        for (int i = tid; i < Bb * CONDD; i += 256) {
            float c = cond[i];
            S[i] = c / (1.f + expf(-c));
        }
        __syncthreads();
        int r = blockIdx.x * 8 + wid;
        const float* wr = W + (size_t)r * CONDD;
        float acc[16];
        #pragma unroll
        for (int b = 0; b < 16; b++) acc[b] = 0.f;
        for (int c0 = 0; c0 < CONDD; c0 += 32) {
            float wv = wr[c0 + lane];
            #pragma unroll
            for (int b = 0; b < 16; b++) acc[b] += wv * S[b * CONDD + c0 + lane];
        }
        #pragma unroll
        for (int b = 0; b < 16; b++) {
            #pragma unroll
            for (int o = 16; o; o >>= 1) acc[b] += __shfl_xor_sync(0xffffffffu, acc[b], o);
        }
        if (lane == 0) {
            float bv = bias[r];
            #pragma unroll
            for (int b = 0; b < 16; b++) g_V[b * NSKEW + r] = acc[b] + bv;
        }
    } else {
        const int bk = blockIdx.x - 252;          // 0..17
        float* Ps = S;                             // [64][68]
        for (int f = tid; f < 64 * 16; f += 256) {
            int r = f >> 4, c4 = (f & 15) * 4;
            *(float4*)(Ps + r * 68 + c4) =
                *(const float4*)(P + (size_t)(bk * 64 + r) * Dd + c4);
        }
        __syncthreads();
        const int a0 = (tid >> 4) * 4, b0 = (tid & 15) * 4;
        float acc[4][4] = {};
        #pragma unroll 4
        for (int r = 0; r < 64; ++r) {
            float4 av = *(const float4*)(Ps + r * 68 + a0);
            float4 bv = *(const float4*)(Ps + r * 68 + b0);
            acc[0][0] += av.x * bv.x; acc[0][1] += av.x * bv.y; acc[0][2] += av.x * bv.z; acc[0][3] += av.x * bv.w;
            acc[1][0] += av.y * bv.x; acc[1][1] += av.y * bv.y; acc[1][2] += av.y * bv.z; acc[1][3] += av.y * bv.w;
            acc[2][0] += av.z * bv.x; acc[2][1] += av.z * bv.y; acc[2][2] += av.z * bv.z; acc[2][3] += av.z * bv.w;
            acc[3][0] += av.w * bv.x; acc[3][1] += av.w * bv.y; acc[3][2] += av.w * bv.z; acc[3][3] += av.w * bv.w;
        }
        float* Gp = g_Gpart + bk * 4096;
        #pragma unroll
        for (int m = 0; m < 4; ++m)
            *(float4*)(Gp + (a0 + m) * 64 + b0) =
                make_float4(acc[m][0], acc[m][1], acc[m][2], acc[m][3]);
    }
}

// =============================================================================
// Kernel 2: sign-exact LAPACK R via top-block recursion, then R^{-1}.
// =============================================================================
__global__ void __launch_bounds__(128) k_rsign(const float* __restrict__ P) {
    extern __shared__ float sm[];
    float* B = sm;                  // [64][RS]
    float* G = sm + 64 * RS;        // [64][RS]
    float* M = sm + 2 * 64 * RS;    // [64][RS]  (reused as Rinv scratch)
    __shared__ float u[64], coef[64];
    __shared__ float s_beta, s_ts, s_amb;
    const int tid = threadIdx.x;

    for (int idx = tid; idx < 4096; idx += 128) {
        int i = idx >> 6, c = idx & 63;
        B[i * RS + c] = P[(size_t)i * Dd + c];
        float g = 0.f;
        #pragma unroll
        for (int t = 0; t < GPARTS; ++t) g += g_Gpart[t * 4096 + idx];
        G[i * RS + c] = g;
        M[i * RS + c] = 0.f;
    }
    __syncthreads();

    for (int j = 0; j < 64; ++j) {
        if (tid == 0) {
            float a = B[j * RS + j];
            float n2 = G[j * RS + j] - M[j * RS + j];
            float nrm = sqrtf(fmaxf(n2, 0.f));
            float beta = (a >= 0.f) ? -nrm : nrm;   // LAPACK sign convention
            float tau = (beta - a) / beta;
            float scl = 1.f / (a - beta);
            s_beta = beta; s_ts = tau * scl * scl; s_amb = a - beta;
        }
        __syncthreads();
        if (tid < 64) {
            int c = tid;
            u[c] = G[j * RS + c] - M[j * RS + c] - s_beta * B[j * RS + c];
        } else {
            int i = tid - 64;
            float vr;
            if (i > j)       vr = B[i * RS + j];
            else if (i == j) vr = s_amb;
            else             vr = 0.f;
            coef[i] = s_ts * vr;
        }
        __syncthreads();
        const int nrows = 64 - j;
        for (int idx = tid; idx < nrows * 64; idx += 128) {
            int i = j + (idx >> 6), c = idx & 63;
            B[i * RS + c] -= coef[i] * u[c];
        }
        __syncthreads();
        if (tid < 64) {
            int c = tid;
            if (c < j)       B[j * RS + c] = 0.f;
            else if (c == j) B[j * RS + c] = s_beta;
        } else {
            int i = tid - 64;
            if (i > j) B[i * RS + j] = 0.f;
        }
        __syncthreads();
        for (int idx = tid; idx < 4096; idx += 128) {
            int a = idx >> 6, b2 = idx & 63;
            M[a * RS + b2] += B[j * RS + a] * B[j * RS + b2];
        }
        __syncthreads();
    }

    float* X = M;   // reuse
    if (tid < 64) {
        const int c = tid;
        for (int i = 63; i >= 0; --i) {
            float s = (i == c) ? 1.f : 0.f;
            for (int k = i + 1; k < 64; ++k) s -= B[i * RS + k] * X[k * RS + c];
            X[i * RS + c] = s / B[i * RS + i];
        }
    }
    __syncthreads();
    for (int idx = tid; idx < 4096; idx += 128)
        g_Rinv[idx] = X[(idx >> 6) * RS + (idx & 63)];
}

// =============================================================================
// Kernel 3: fused  [blocks 0..17]  U = P * Rinv ; [blocks 18..33] expm
// =============================================================================
static __device__ __forceinline__ void mm_horner(float* __restrict__ out,
                                                 const float* __restrict__ As,
                                                 const float* __restrict__ X,
                                                 float invk, int r0, int c0) {
    ull acc[4][2] = {};
    #pragma unroll 4
    for (int d = 0; d < 64; ++d) {
        float4 a4 = *(const float4*)(As + d * MP + r0);
        ulonglong2 bv = *(const ulonglong2*)(X + d * MP + c0);
        ull a0 = pack2(a4.x, a4.x), a1 = pack2(a4.y, a4.y);
        ull a2 = pack2(a4.z, a4.z), a3 = pack2(a4.w, a4.w);
        acc[0][0] = fma2(a0, bv.x, acc[0][0]); acc[0][1] = fma2(a0, bv.y, acc[0][1]);
        acc[1][0] = fma2(a1, bv.x, acc[1][0]); acc[1][1] = fma2(a1, bv.y, acc[1][1]);
        acc[2][0] = fma2(a2, bv.x, acc[2][0]); acc[2][1] = fma2(a2, bv.y, acc[2][1]);
        acc[3][0] = fma2(a3, bv.x, acc[3][0]); acc[3][1] = fma2(a3, bv.y, acc[3][1]);
    }
    const float nk = -invk;
    #pragma unroll
    for (int m = 0; m < 4; ++m) {
        float s0, s1, s2, s3;
        unpack2(acc[m][0], s0, s1);
        unpack2(acc[m][1], s2, s3);
        float4 o;
        o.x = nk * s0 + ((r0 + m == c0 + 0) ? 1.f : 0.f);
        o.y = nk * s1 + ((r0 + m == c0 + 1) ? 1.f : 0.f);
        o.z = nk * s2 + ((r0 + m == c0 + 2) ? 1.f : 0.f);
        o.w = nk * s3 + ((r0 + m == c0 + 3) ? 1.f : 0.f);
        *(float4*)(out + (r0 + m) * MP + c0) = o;
    }
}

static __device__ __forceinline__ void mm_sq(float* __restrict__ out,
                                             const float* __restrict__ XT,
                                             const float* __restrict__ X,
                                             int r0, int c0) {
    ull acc[4][2] = {};
    #pragma unroll 4
    for (int d = 0; d < 64; ++d) {
        float4 a4 = *(const float4*)(XT + d * MPT + r0);
        ulonglong2 bv = *(const ulonglong2*)(X + d * MP + c0);
        ull a0 = pack2(a4.x, a4.x), a1 = pack2(a4.y, a4.y);
        ull a2 = pack2(a4.z, a4.z), a3 = pack2(a4.w, a4.w);
        acc[0][0] = fma2(a0, bv.x, acc[0][0]); acc[0][1] = fma2(a0, bv.y, acc[0][1]);
        acc[1][0] = fma2(a1, bv.x, acc[1][0]); acc[1][1] = fma2(a1, bv.y, acc[1][1]);
        acc[2][0] = fma2(a2, bv.x, acc[2][0]); acc[2][1] = fma2(a2, bv.y, acc[2][1]);
        acc[3][0] = fma2(a3, bv.x, acc[3][0]); acc[3][1] = fma2(a3, bv.y, acc[3][1]);
    }
    #pragma unroll
    for (int m = 0; m < 4; ++m) {
        float s0, s1, s2, s3;
        unpack2(acc[m][0], s0, s1);
        unpack2(acc[m][1], s2, s3);
        *(float4*)(out + (r0 + m) * MP + c0) = make_float4(s0, s1, s2, s3);
    }
}

__global__ void __launch_bounds__(256) k_prep1(const float* __restrict__ P) {
    extern __shared__ float sm[];
    const int tid = threadIdx.x;

    if (blockIdx.x < 18) {
        float* PsT = sm;              // [64][68]  PsT[k][r]
        float* Ri  = sm + 64 * 68;    // [64][68]  Ri[k][d]
        const int n0 = blockIdx.x * 64;
        for (int f = tid; f < 64 * 16; f += 256) {
            int r = f >> 4, k4 = (f & 15) * 4;
            float4 v = *(const float4*)(P + (size_t)(n0 + r) * Dd + k4);
            PsT[(k4 + 0) * 68 + r] = v.x;
            PsT[(k4 + 1) * 68 + r] = v.y;
            PsT[(k4 + 2) * 68 + r] = v.z;
            PsT[(k4 + 3) * 68 + r] = v.w;
        }
        for (int f = tid; f < 64 * 16; f += 256) {
            int k = f >> 4, d4 = (f & 15) * 4;
            *(float4*)(Ri + k * 68 + d4) = *(const float4*)(g_Rinv + k * 64 + d4);
        }
        __syncthreads();
        const int r0 = (tid >> 4) * 4, d0 = (tid & 15) * 4;
        float acc[4][4] = {};
        #pragma unroll 4
        for (int k = 0; k < 64; ++k) {
            float4 av = *(const float4*)(PsT + k * 68 + r0);
            float4 bv = *(const float4*)(Ri + k * 68 + d0);
            acc[0][0] += av.x * bv.x; acc[0][1] += av.x * bv.y; acc[0][2] += av.x * bv.z; acc[0][3] += av.x * bv.w;
            acc[1][0] += av.y * bv.x; acc[1][1] += av.y * bv.y; acc[1][2] += av.y * bv.z; acc[1][3] += av.y * bv.w;
            acc[2][0] += av.z * bv.x; acc[2][1] += av.z * bv.y; acc[2][2] += av.z * bv.z; acc[2][3] += av.z * bv.w;
            acc[3][0] += av.w * bv.x; acc[3][1] += av.w * bv.y; acc[3][2] += av.w * bv.z; acc[3][3] += av.w * bv.w;
        }
        #pragma unroll
        for (int m = 0; m < 4; ++m) {
            int n = n0 + r0 + m;
            *(float4*)(g_U + (size_t)n * Dd + d0) =
                make_float4(acc[m][0], acc[m][1], acc[m][2], acc[m][3]);
            #pragma unroll
            for (int q = 0; q < 4; ++q)
                g_Ut[(size_t)(d0 + q) * Nn + n] = acc[m][q];
        }
    } else {
        float* As = sm;
        float* X0 = As + 64 * MP;
        float* X1 = X0 + 64 * MP;
        float* XT = X1 + 64 * MP;
        __shared__ float rowsum[64];
        __shared__ int s_s;
        const int r0 = (tid >> 4) * 4, c0 = (tid & 15) * 4;
        const int b = blockIdx.x - 18;
        const float* v = g_V + b * NSKEW;

        for (int t = tid; t < 4096; t += 256) {
            int i = t >> 6, j = t & 63;
            float val = 0.f;
            if (i < j)      val =  v[i * (127 - i) / 2 + (j - i - 1)];
            else if (i > j) val = -v[j * (127 - j) / 2 + (i - j - 1)];
            As[i * MP + j] = val;
        }
        __syncthreads();
        if (tid < 64) {
            float s = 0.f;
            for (int j = 0; j < 64; j++) s += fabsf(As[tid * MP + j]);
            rowsum[tid] = s;
        }
        __syncthreads();
        if (tid == 0) {
            float nrm = 0.f;
            for (int i = 0; i < 64; i++) nrm = fmaxf(nrm, rowsum[i]);
            int s = 0; float nn = nrm;
            while (nn > 0.5f && s < 40) { nn *= 0.5f; s++; }
            s_s = s;
        }
        __syncthreads();
        const int s = s_s;
        const float sc = exp2f((float)(-s));
        for (int t = tid; t < 4096; t += 256) { int i = t >> 6, j = t & 63; As[i * MP + j] *= sc; }
        __syncthreads();

        for (int t = tid; t < 4096; t += 256) {
            int i = t >> 6, j = t & 63;
            X0[i * MP + j] = ((i == j) ? 1.f : 0.f) + As[i * MP + j] * 0.125f;
        }
        float* Xa = X0; float* Xb = X1;
        for (int k = 7; k >= 1; --k) {
            __syncthreads();
            mm_horner(Xb, As, Xa, 1.f / (float)k, r0, c0);
            float* t = Xa; Xa = Xb; Xb = t;
        }
        for (int q = 0; q < s; q++) {
            __syncthreads();
            for (int t = tid; t < 4096; t += 256) {
                int i = t >> 6, j = t & 63;
                XT[j * MPT + i] = Xa[i * MP + j];
            }
            __syncthreads();
            mm_sq(Xb, XT, Xa, r0, c0);
            float* t = Xa; Xa = Xb; Xb = t;
        }
        __syncthreads();
        for (int t = tid; t < 4096; t += 256) {
            int i = t >> 6, j = t & 63;
            g_RmI[b * 4096 + t] = Xa[i * MP + j] - ((i == j) ? 1.f : 0.f);
        }
    }
}

// =============================================================================
// Kernel 4: Y = (X U)(R - I).  64-row tiles, 256 blocks, 256 threads.
// ROW-MAJOR smem staging (no transpose -> no 8-way bank conflicts);
// inner loop walks k in groups of 4 with X row fragments in registers.
// =============================================================================
__global__ void __launch_bounds__(256) k_p1(const float* __restrict__ X,
                                            float* __restrict__ Y) {
    extern __shared__ float sm[];
    float* Xs = sm;                  // [64][68]  Xs[r][k]   (row-major)
    float* Us = sm + 64 * P1S;       // [64][68]  Us[k][c]
    float* Ms = Us + 64 * P1S;       // [64][68]  Ms[d][e]

    const int tid = threadIdx.x;
    const int rg = tid >> 4, cg = tid & 15;
    const int r0 = rg * 4, c0 = cg * 4;
    const size_t rowbase = (size_t)blockIdx.x * 64;
    const float* Xg = X + rowbase * Nn;
    const int b = blockIdx.x >> 4;

    const float* Mg = g_RmI + b * 4096;
    for (int i = tid; i < 4096; i += 256) {
        int d = i >> 6, e = i & 63;
        Ms[d * P1S + e] = Mg[i];
    }

    ull acc[4][2] = {};
    for (int kc = 0; kc < Nn; kc += 64) {
        __syncthreads();
        // stage X tile ROW-MAJOR (contiguous float4 stores, conflict-free)
        #pragma unroll
        for (int it = 0; it < 4; ++it) {
            int f4 = tid + 256 * it;
            int r  = f4 >> 4;
            int kq = (f4 & 15) * 4;
            *(float4*)(Xs + r * P1S + kq) =
                *(const float4*)(Xg + (size_t)r * Nn + kc + kq);
        }
        // stage U chunk: Us[k][d]
        #pragma unroll
        for (int it = 0; it < 4; ++it) {
            int f4 = tid + 256 * it;
            int kk = f4 >> 4;
            int dq = (f4 & 15) * 4;
            *(float4*)(Us + kk * P1S + dq) =
                *(const float4*)(g_U + (size_t)(kc + kk) * Dd + dq);
        }
        __syncthreads();
        #pragma unroll 2
        for (int k4 = 0; k4 < 64; k4 += 4) {
            float xr[4][4];
            #pragma unroll
            for (int m = 0; m < 4; ++m)
                *(float4*)xr[m] = *(const float4*)(Xs + (r0 + m) * P1S + k4);
            #pragma unroll
            for (int kk = 0; kk < 4; ++kk) {
                ulonglong2 uv = *(const ulonglong2*)(Us + (k4 + kk) * P1S + c0);
                ull x0 = pack2(xr[0][kk], xr[0][kk]);
                ull x1 = pack2(xr[1][kk], xr[1][kk]);
                ull x2 = pack2(xr[2][kk], xr[2][kk]);
                ull x3 = pack2(xr[3][kk], xr[3][kk]);
                acc[0][0] = fma2(x0, uv.x, acc[0][0]); acc[0][1] = fma2(x0, uv.y, acc[0][1]);
                acc[1][0] = fma2(x1, uv.x, acc[1][0]); acc[1][1] = fma2(x1, uv.y, acc[1][1]);
                acc[2][0] = fma2(x2, uv.x, acc[2][0]); acc[2][1] = fma2(x2, uv.y, acc[2][1]);
                acc[3][0] = fma2(x3, uv.x, acc[3][0]); acc[3][1] = fma2(x3, uv.y, acc[3][1]);
            }
        }
    }
    __syncthreads();
    // write z ROW-MAJOR into the Xs region (contiguous float4, conflict-free)
    float* Zs = Xs;
    #pragma unroll
    for (int m = 0; m < 4; ++m) {
        float e0, e1, e2, e3;
        unpack2(acc[m][0], e0, e1);
        unpack2(acc[m][1], e2, e3);
        *(float4*)(Zs + (r0 + m) * P1S + c0) = make_float4(e0, e1, e2, e3);
    }
    __syncthreads();
    // y = z (R - I), same row-major k4 pattern over d
    ull yac[4][2] = {};
    #pragma unroll 2
    for (int d4 = 0; d4 < 64; d4 += 4) {
        float zr[4][4];
        #pragma unroll
        for (int m = 0; m < 4; ++m)
            *(float4*)zr[m] = *(const float4*)(Zs + (r0 + m) * P1S + d4);
        #pragma unroll
        for (int dd = 0; dd < 4; ++dd) {
            ulonglong2 mv = *(const ulonglong2*)(Ms + (d4 + dd) * P1S + c0);
            ull z0 = pack2(zr[0][dd], zr[0][dd]);
            ull z1 = pack2(zr[1][dd], zr[1][dd]);
            ull z2 = pack2(zr[2][dd], zr[2][dd]);
            ull z3 = pack2(zr[3][dd], zr[3][dd]);
            yac[0][0] = fma2(z0, mv.x, yac[0][0]); yac[0][1] = fma2(z0, mv.y, yac[0][1]);
            yac[1][0] = fma2(z1, mv.x, yac[1][0]); yac[1][1] = fma2(z1, mv.y, yac[1][1]);
            yac[2][0] = fma2(z2, mv.x, yac[2][0]); yac[2][1] = fma2(z2, mv.y, yac[2][1]);
            yac[3][0] = fma2(z3, mv.x, yac[3][0]); yac[3][1] = fma2(z3, mv.y, yac[3][1]);
        }
    }
    #pragma unroll
    for (int m = 0; m < 4; ++m) {
        float e0, e1, e2, e3;
        unpack2(yac[m][0], e0, e1);
        unpack2(yac[m][1], e2, e3);
        *(float4*)(Y + (rowbase + r0 + m) * Dd + c0) = make_float4(e0, e1, e2, e3);
    }
}

// =============================================================================
// Kernel 5: out = X + Y U^T.  Block tile 64 rows x 128 n-cols; grid (9, 256).
// ROW-MAJOR Y staging; inner loop walks d in groups of 4.
// =============================================================================
__global__ void __launch_bounds__(256) k_p2(const float* __restrict__ X,
                                            const float* __restrict__ Y,
                                            float* __restrict__ out) {
    extern __shared__ float sm[];
    float* Ys  = sm;                 // [64][68]   Ys[r][d]  (row-major)
    float* Uts = sm + 64 * P2SY;     // [64][132]  Uts[d][n]

    const int tid = threadIdx.x;
    const int rg = tid >> 4, cg = tid & 15;
    const int r0 = rg * 4;
    const int n0 = cg * 8;
    const size_t rowbase = (size_t)blockIdx.y * 64;
    const int nbase = blockIdx.x * 128;

    // stage Y tile ROW-MAJOR (contiguous float4, conflict-free)
    #pragma unroll
    for (int it = 0; it < 4; ++it) {
        int f4 = tid + 256 * it;
        int r  = f4 >> 4;
        int dq = (f4 & 15) * 4;
        *(float4*)(Ys + r * P2SY + dq) =
            *(const float4*)(Y + (rowbase + r) * Dd + dq);
    }
    #pragma unroll
    for (int it = 0; it < 8; ++it) {
        int f4 = tid + 256 * it;
        int d  = f4 >> 5;
        int nq = (f4 & 31) * 4;
        *(float4*)(Uts + d * P2SU + nq) =
            *(const float4*)(g_Ut + (size_t)d * Nn + nbase + nq);
    }
    __syncthreads();

    ull acc[4][4] = {};
    #pragma unroll 2
    for (int d4 = 0; d4 < 64; d4 += 4) {
        float yr[4][4];
        #pragma unroll
        for (int m = 0; m < 4; ++m)
            *(float4*)yr[m] = *(const float4*)(Ys + (r0 + m) * P2SY + d4);
        #pragma unroll
        for (int dd = 0; dd < 4; ++dd) {
            ulonglong2 u0 = *(const ulonglong2*)(Uts + (d4 + dd) * P2SU + n0);
            ulonglong2 u1 = *(const ulonglong2*)(Uts + (d4 + dd) * P2SU + n0 + 4);
            ull y0 = pack2(yr[0][dd], yr[0][dd]);
            ull y1 = pack2(yr[1][dd], yr[1][dd]);
            ull y2 = pack2(yr[2][dd], yr[2][dd]);
            ull y3 = pack2(yr[3][dd], yr[3][dd]);
            acc[0][0] = fma2(y0, u0.x, acc[0][0]); acc[0][1] = fma2(y0, u0.y, acc[0][1]);
            acc[0][2] = fma2(y0, u1.x, acc[0][2]); acc[0][3] = fma2(y0, u1.y, acc[0][3]);
            acc[1][0] = fma2(y1, u0.x, acc[1][0]); acc[1][1] = fma2(y1, u0.y, acc[1][1]);
            acc[1][2] = fma2(y1, u1.x, acc[1][2]); acc[1][3] = fma2(y1, u1.y, acc[1][3]);
            acc[2][0] = fma2(y2, u0.x, acc[2][0]); acc[2][1] = fma2(y2, u0.y, acc[2][1]);
            acc[2][2] = fma2(y2, u1.x, acc[2][2]); acc[2][3] = fma2(y2, u1.y, acc[2][3]);
            acc[3][0] = fma2(y3, u0.x, acc[3][0]); acc[3][1] = fma2(y3, u0.y, acc[3][1]);
            acc[3][2] = fma2(y3, u1.x, acc[3][2]); acc[3][3] = fma2(y3, u1.y, acc[3][3]);
        }
    }

    #pragma unroll
    for (int m = 0; m < 4; ++m) {
        const size_t row = rowbase + r0 + m;
        const float* xr = X + row * Nn + nbase + n0;
        float* orow = out + row * Nn + nbase + n0;
        float4 xa = *(const float4*)(xr);
        float4 xb = *(const float4*)(xr + 4);
        float e0, e1, e2, e3;
        unpack2(acc[m][0], e0, e1); unpack2(acc[m][1], e2, e3);
        *(float4*)(orow) = make_float4(xa.x + e0, xa.y + e1, xa.z + e2, xa.w + e3);
        unpack2(acc[m][2], e0, e1); unpack2(acc[m][3], e2, e3);
        *(float4*)(orow + 4) = make_float4(xb.x + e0, xb.y + e1, xb.z + e2, xb.w + e3);
    }
}

// =============================================================================
extern "C" void kernel_launch(void* const* d_in, const int* in_sizes, int n_in,
                              void* d_out, int out_size) {
    const float* x    = (const float*)d_in[0];
    const float* cond = (const float*)d_in[1];
    const float* P    = (const float*)d_in[2];
    const float* W    = (const float*)d_in[3];
    const float* bias = (const float*)d_in[4];
    float* out = (float*)d_out;

    float* Yg = nullptr;
    cudaGetSymbolAddress((void**)&Yg, g_Y);

    const int smem_prep0 = Bb * CONDD * 4;                 // 73728
    const int smem_rsign = 3 * 64 * RS * 4;                // 49920
    const int smem_prep1 = (3 * MP + MPT) * 64 * 4;        // 69632
    const int smem_p1    = 3 * 64 * P1S * 4;               // 52224
    const int smem_p2    = 64 * P2SY * 4 + 64 * P2SU * 4;  // 51200

    cudaFuncSetAttribute(k_prep0, cudaFuncAttributeMaxDynamicSharedMemorySize, smem_prep0);
    cudaFuncSetAttribute(k_rsign, cudaFuncAttributeMaxDynamicSharedMemorySize, smem_rsign);
    cudaFuncSetAttribute(k_prep1, cudaFuncAttributeMaxDynamicSharedMemorySize, smem_prep1);
    cudaFuncSetAttribute(k_p1,    cudaFuncAttributeMaxDynamicSharedMemorySize, smem_p1);
    cudaFuncSetAttribute(k_p2,    cudaFuncAttributeMaxDynamicSharedMemorySize, smem_p2);

    // Kernel order: p1 stays in profile slot #4 to verify the LDS-fix prediction.
    k_prep0<<<252 + GPARTS, 256, smem_prep0>>>(cond, W, bias, P);
    k_rsign<<<1, 128, smem_rsign>>>(P);
    k_prep1<<<18 + Bb, 256, smem_prep1>>>(P);
    k_p1   <<<(Bb * Tt) / 64, 256, smem_p1>>>(x, Yg);
    dim3 g2(Nn / 128, (Bb * Tt) / 64);
    k_p2   <<<g2, 256, smem_p2>>>(x, Yg, out);
}